// round 1
// baseline (speedup 1.0000x reference)
#include <cuda_runtime.h>
#include <math.h>

#define B 2
#define L 2048
#define D 2048
#define H 16
#define HKV 4
#define HD 128
#define GROUPS (H / HKV)
#define M_TOK (B * L)          // 4096 tokens
#define KVDIM (2 * HKV * HD)   // 1024
#define KDIM  (HKV * HD)       // 512

// ---------------- scratch (static device arrays; no allocation allowed) ----
__device__ float g_Q [(size_t)M_TOK * D];      // roped Q   (b,l,h,d)
__device__ float g_KV[(size_t)M_TOK * KVDIM];  // raw kv projection
__device__ float g_K [(size_t)M_TOK * KDIM];   // roped K   (b,l,hkv,d)
__device__ float g_V [(size_t)M_TOK * KDIM];   // V         (b,l,hkv,d)
__device__ float g_A [(size_t)M_TOK * D];      // attention output (b,l,h,d)

// ---------------------------------------------------------------------------
// GEMM: C[M][N] = A[M][K] * W[N][K]^T + bias[N]     (both operands K-contig)
// BM=BN=128, BK=16, 256 threads, 8x8 per thread.
// Requires M%128==0, N%128==0, K%16==0 (true for all calls here).
// ---------------------------------------------------------------------------
__global__ __launch_bounds__(256) void gemm_nt_bias(
    const float* __restrict__ A, const float* __restrict__ W,
    const float* __restrict__ bias, float* __restrict__ C,
    int M, int N, int K)
{
    __shared__ float As[16][128];
    __shared__ float Ws[16][128];

    const int tid = threadIdx.x;
    const int bm = blockIdx.y * 128;
    const int bn = blockIdx.x * 128;
    const int ty = tid >> 4;      // 0..15
    const int tx = tid & 15;      // 0..15
    const int lr = tid >> 2;      // 0..63 (load row)
    const int lv = tid & 3;       // 0..3  (float4 within 16-wide k slab)

    float acc[8][8];
#pragma unroll
    for (int i = 0; i < 8; i++)
#pragma unroll
        for (int j = 0; j < 8; j++) acc[i][j] = 0.f;

    for (int k0 = 0; k0 < K; k0 += 16) {
#pragma unroll
        for (int i = 0; i < 2; i++) {
            const int r = lr + i * 64;
            float4 a = *(const float4*)&A[(size_t)(bm + r) * K + k0 + lv * 4];
            As[lv * 4 + 0][r] = a.x; As[lv * 4 + 1][r] = a.y;
            As[lv * 4 + 2][r] = a.z; As[lv * 4 + 3][r] = a.w;
            float4 w = *(const float4*)&W[(size_t)(bn + r) * K + k0 + lv * 4];
            Ws[lv * 4 + 0][r] = w.x; Ws[lv * 4 + 1][r] = w.y;
            Ws[lv * 4 + 2][r] = w.z; Ws[lv * 4 + 3][r] = w.w;
        }
        __syncthreads();

#pragma unroll
        for (int kk = 0; kk < 16; kk++) {
            float4 a0 = *(const float4*)&As[kk][ty * 8];
            float4 a1 = *(const float4*)&As[kk][ty * 8 + 4];
            float4 b0 = *(const float4*)&Ws[kk][tx * 8];
            float4 b1 = *(const float4*)&Ws[kk][tx * 8 + 4];
            float av[8] = {a0.x, a0.y, a0.z, a0.w, a1.x, a1.y, a1.z, a1.w};
            float bv[8] = {b0.x, b0.y, b0.z, b0.w, b1.x, b1.y, b1.z, b1.w};
#pragma unroll
            for (int i = 0; i < 8; i++)
#pragma unroll
                for (int j = 0; j < 8; j++)
                    acc[i][j] = fmaf(av[i], bv[j], acc[i][j]);
        }
        __syncthreads();
    }

    float4 bsl0 = *(const float4*)&bias[bn + tx * 8];
    float4 bsl1 = *(const float4*)&bias[bn + tx * 8 + 4];
#pragma unroll
    for (int i = 0; i < 8; i++) {
        const int row = bm + ty * 8 + i;
        float4 o0 = make_float4(acc[i][0] + bsl0.x, acc[i][1] + bsl0.y,
                                acc[i][2] + bsl0.z, acc[i][3] + bsl0.w);
        float4 o1 = make_float4(acc[i][4] + bsl1.x, acc[i][5] + bsl1.y,
                                acc[i][6] + bsl1.z, acc[i][7] + bsl1.w);
        *(float4*)&C[(size_t)row * N + bn + tx * 8]     = o0;
        *(float4*)&C[(size_t)row * N + bn + tx * 8 + 4] = o1;
    }
}

// ---------------------------------------------------------------------------
// RoPE on Q (in place) and K (KV -> K split), plus V split. One block / token.
// rotate_half: out[d]     = t[d]*cos[d]     - t[d+64]*sin[d]       (d < 64)
//              out[d+64]  = t[d+64]*cos[d+64] + t[d]*sin[d+64]
// ---------------------------------------------------------------------------
__global__ __launch_bounds__(256) void rope_split(
    const float* __restrict__ cosb, const float* __restrict__ sinb,
    float* __restrict__ Q, const float* __restrict__ KV,
    float* __restrict__ K, float* __restrict__ V)
{
    const int tok = blockIdx.x;
    const int tid = threadIdx.x;
    const float* c = cosb + (size_t)tok * HD;
    const float* s = sinb + (size_t)tok * HD;

    // Q: 16 heads x 64 pairs
    for (int p = tid; p < H * 64; p += 256) {
        const int h = p >> 6, d = p & 63;
        const size_t base = (size_t)tok * D + h * HD;
        const float a = Q[base + d], b2 = Q[base + d + 64];
        Q[base + d]      = a  * c[d]      - b2 * s[d];
        Q[base + d + 64] = b2 * c[d + 64] + a  * s[d + 64];
    }
    // K: 4 heads x 64 pairs (kv slot 0)
    for (int p = tid; p < HKV * 64; p += 256) {
        const int h = p >> 6, d = p & 63;
        const size_t ib = (size_t)tok * KVDIM + h * HD;
        const size_t ob = (size_t)tok * KDIM  + h * HD;
        const float a = KV[ib + d], b2 = KV[ib + d + 64];
        K[ob + d]      = a  * c[d]      - b2 * s[d];
        K[ob + d + 64] = b2 * c[d + 64] + a  * s[d + 64];
    }
    // V copy (kv slot 1)
    for (int e = tid; e < KDIM; e += 256)
        V[(size_t)tok * KDIM + e] = KV[(size_t)tok * KVDIM + KDIM + e];
}

// ---------------------------------------------------------------------------
// Causal GQA flash attention, fp32.
// Block: 64 queries (8 warps x 8 rows), key tiles of 32 (lane == key).
// smem rows padded to 132 floats -> conflict-free float4 LDS.
// ---------------------------------------------------------------------------
#define FA_BM 64
#define FA_BN 32
#define FA_PAD 132

__global__ __launch_bounds__(256) void flash_attn(
    const float* __restrict__ Q, const float* __restrict__ K,
    const float* __restrict__ V, float* __restrict__ O)
{
    extern __shared__ float smem[];
    float* Qs = smem;                        // 64 * 132
    float* Ks = Qs + FA_BM * FA_PAD;         // 32 * 132
    float* Vs = Ks + FA_BN * FA_PAD;         // 32 * 132

    const int tid  = threadIdx.x;
    const int w    = tid >> 5;
    const int lane = tid & 31;
    const int m0   = blockIdx.x * FA_BM;
    const int bh   = blockIdx.y;
    const int b    = bh / H;
    const int h    = bh % H;
    const int kvh  = h / GROUPS;
    const float scale = 0.08838834764831845f;   // 1/sqrt(128)

    // load Q tile (64 rows x 128)
    {
        const int f = tid & 31, r0 = tid >> 5;
#pragma unroll
        for (int i = 0; i < 8; i++) {
            const int row = r0 + i * 8;
            const size_t g = (((size_t)(b * L + m0 + row)) * H + h) * HD + f * 4;
            *(float4*)&Qs[row * FA_PAD + f * 4] = *(const float4*)&Q[g];
        }
    }
    __syncthreads();

    float4 o4[8];
    float m_r[8], l_r[8];
#pragma unroll
    for (int r = 0; r < 8; r++) {
        o4[r] = make_float4(0.f, 0.f, 0.f, 0.f);
        m_r[r] = -INFINITY;
        l_r[r] = 0.f;
    }

    const int ntiles = (m0 + FA_BM) / FA_BN;
    for (int t = 0; t < ntiles; t++) {
        const int n0 = t * FA_BN;
        // load K,V tiles (32 rows x 128 each)
        {
            const int f = tid & 31, r0 = tid >> 5;
#pragma unroll
            for (int i = 0; i < 4; i++) {
                const int kr = r0 + i * 8;
                const size_t g = (((size_t)(b * L + n0 + kr)) * HKV + kvh) * HD + f * 4;
                *(float4*)&Ks[kr * FA_PAD + f * 4] = *(const float4*)&K[g];
                *(float4*)&Vs[kr * FA_PAD + f * 4] = *(const float4*)&V[g];
            }
        }
        __syncthreads();

        // scores: lane = key index, each warp covers 8 query rows
        float s[8];
#pragma unroll
        for (int r = 0; r < 8; r++) s[r] = 0.f;
#pragma unroll
        for (int d4 = 0; d4 < 32; d4++) {
            float4 k4 = *(const float4*)&Ks[lane * FA_PAD + d4 * 4];
#pragma unroll
            for (int r = 0; r < 8; r++) {
                float4 q4 = *(const float4*)&Qs[(w * 8 + r) * FA_PAD + d4 * 4];
                s[r] = fmaf(q4.x, k4.x, s[r]);
                s[r] = fmaf(q4.y, k4.y, s[r]);
                s[r] = fmaf(q4.z, k4.z, s[r]);
                s[r] = fmaf(q4.w, k4.w, s[r]);
            }
        }

        const int keyg = n0 + lane;
        float p[8];
#pragma unroll
        for (int r = 0; r < 8; r++) {
            const int qg = m0 + w * 8 + r;
            float sv = (keyg <= qg) ? s[r] * scale : -INFINITY;
            float mx = sv;
#pragma unroll
            for (int off = 16; off; off >>= 1)
                mx = fmaxf(mx, __shfl_xor_sync(0xffffffffu, mx, off));
            const float m_new = fmaxf(m_r[r], mx);
            float pv = __expf(sv - m_new);
            float ps = pv;
#pragma unroll
            for (int off = 16; off; off >>= 1)
                ps += __shfl_xor_sync(0xffffffffu, ps, off);
            const float alpha = __expf(m_r[r] - m_new);
            l_r[r] = l_r[r] * alpha + ps;
            m_r[r] = m_new;
            o4[r].x *= alpha; o4[r].y *= alpha; o4[r].z *= alpha; o4[r].w *= alpha;
            p[r] = pv;
        }

        // PV: lane owns output dims [lane*4, lane*4+4)
#pragma unroll
        for (int key = 0; key < FA_BN; key++) {
            float4 v4 = *(const float4*)&Vs[key * FA_PAD + lane * 4];
#pragma unroll
            for (int r = 0; r < 8; r++) {
                const float pk = __shfl_sync(0xffffffffu, p[r], key);
                o4[r].x = fmaf(pk, v4.x, o4[r].x);
                o4[r].y = fmaf(pk, v4.y, o4[r].y);
                o4[r].z = fmaf(pk, v4.z, o4[r].z);
                o4[r].w = fmaf(pk, v4.w, o4[r].w);
            }
        }
        __syncthreads();
    }

#pragma unroll
    for (int r = 0; r < 8; r++) {
        const int qg = m0 + w * 8 + r;
        const float inv = 1.f / l_r[r];
        float4 o = make_float4(o4[r].x * inv, o4[r].y * inv,
                               o4[r].z * inv, o4[r].w * inv);
        *(float4*)&O[(((size_t)(b * L + qg)) * H + h) * HD + lane * 4] = o;
    }
}

// ---------------------------------------------------------------------------
extern "C" void kernel_launch(void* const* d_in, const int* in_sizes, int n_in,
                              void* d_out, int out_size)
{
    (void)in_sizes; (void)n_in; (void)out_size;
    const float* x    = (const float*)d_in[0];
    const float* cosb = (const float*)d_in[1];
    const float* sinb = (const float*)d_in[2];
    const float* Wq   = (const float*)d_in[3];
    const float* bq   = (const float*)d_in[4];
    const float* Wkv  = (const float*)d_in[5];
    const float* bkv  = (const float*)d_in[6];
    const float* Wo   = (const float*)d_in[7];
    const float* bo   = (const float*)d_in[8];
    float* out = (float*)d_out;

    float *Qb, *KVb, *Kb, *Vb, *Ab;
    cudaGetSymbolAddress((void**)&Qb,  g_Q);
    cudaGetSymbolAddress((void**)&KVb, g_KV);
    cudaGetSymbolAddress((void**)&Kb,  g_K);
    cudaGetSymbolAddress((void**)&Vb,  g_V);
    cudaGetSymbolAddress((void**)&Ab,  g_A);

    // Q projection:  (4096 x 2048) = x @ Wq^T + bq
    dim3 gq(D / 128, M_TOK / 128);
    gemm_nt_bias<<<gq, 256>>>(x, Wq, bq, Qb, M_TOK, D, D);

    // KV projection: (4096 x 1024) = x @ Wkv^T + bkv
    dim3 gkv(KVDIM / 128, M_TOK / 128);
    gemm_nt_bias<<<gkv, 256>>>(x, Wkv, bkv, KVb, M_TOK, KVDIM, D);

    // RoPE + split
    rope_split<<<M_TOK, 256>>>(cosb, sinb, Qb, KVb, Kb, Vb);

    // Flash attention
    size_t fa_smem = (size_t)(FA_BM * FA_PAD + 2 * FA_BN * FA_PAD) * sizeof(float);
    cudaFuncSetAttribute(flash_attn, cudaFuncAttributeMaxDynamicSharedMemorySize,
                         (int)fa_smem);
    flash_attn<<<dim3(L / FA_BM, B * H), 256, fa_smem>>>(Qb, Kb, Vb, Ab);

    // Output projection: (4096 x 2048) = A @ Wo^T + bo
    gemm_nt_bias<<<gq, 256>>>(Ab, Wo, bo, out, M_TOK, D, D);
}

// round 5
// speedup vs baseline: 1.7124x; 1.7124x over previous
#include <cuda_runtime.h>
#include <cuda_bf16.h>
#include <math.h>
#include <stdint.h>

#define B 2
#define L 2048
#define D 2048
#define H 16
#define HKV 4
#define HD 128
#define GROUPS (H / HKV)
#define M_TOK (B * L)          // 4096 tokens
#define KVDIM (2 * HKV * HD)   // 1024
#define KDIM  (HKV * HD)       // 512

// ---------------- scratch (static device arrays; no allocation allowed) ----
__device__ float g_Q [(size_t)M_TOK * D];
__device__ float g_KV[(size_t)M_TOK * KVDIM];
__device__ float g_K [(size_t)M_TOK * KDIM];
__device__ float g_V [(size_t)M_TOK * KDIM];
__device__ float g_A [(size_t)M_TOK * D];
__device__ __nv_bfloat16 g_xh[(size_t)M_TOK * D];
__device__ __nv_bfloat16 g_xl[(size_t)M_TOK * D];
__device__ __nv_bfloat16 g_wh[(size_t)D * D];
__device__ __nv_bfloat16 g_wl[(size_t)D * D];

// ======================= helpers ==========================================
__device__ __forceinline__ uint32_t smem_u32(const void* p) {
    uint32_t a;
    asm("{ .reg .u64 t; cvta.to.shared.u64 t, %1; cvt.u32.u64 %0, t; }"
        : "=r"(a) : "l"(p));
    return a;
}
#define SWZ128(off) ((off) ^ (((off) >> 3) & 0x70))

__device__ __forceinline__ void ldsm4(uint32_t addr, uint32_t* r) {
    asm volatile("ldmatrix.sync.aligned.m8n8.x4.shared.b16 {%0,%1,%2,%3}, [%4];"
                 : "=r"(r[0]), "=r"(r[1]), "=r"(r[2]), "=r"(r[3]) : "r"(addr));
}
__device__ __forceinline__ void mma_bf16(float* c, const uint32_t* a,
                                         const uint32_t* b) {
    asm volatile(
        "mma.sync.aligned.m16n8k16.row.col.f32.bf16.bf16.f32 "
        "{%0,%1,%2,%3}, {%4,%5,%6,%7}, {%8,%9}, {%0,%1,%2,%3};"
        : "+f"(c[0]), "+f"(c[1]), "+f"(c[2]), "+f"(c[3])
        : "r"(a[0]), "r"(a[1]), "r"(a[2]), "r"(a[3]), "r"(b[0]), "r"(b[1]));
}
__device__ __forceinline__ void cp_async16(uint32_t dst, const void* src) {
    asm volatile("cp.async.cg.shared.global [%0], [%1], 16;"
                 :: "r"(dst), "l"(src));
}
#define CP_COMMIT() asm volatile("cp.async.commit_group;" ::: "memory")
#define CP_WAIT(N)  asm volatile("cp.async.wait_group %0;" :: "n"(N) : "memory")

// ======================= hi/lo split conversion ===========================
__global__ __launch_bounds__(256) void cvt_hilo(
    const float* __restrict__ src,
    __nv_bfloat16* __restrict__ hi, __nv_bfloat16* __restrict__ lo, int n4)
{
    int i = blockIdx.x * blockDim.x + threadIdx.x;
    if (i >= n4) return;
    float4 v = ((const float4*)src)[i];
    __nv_bfloat16 h0 = __float2bfloat16(v.x);
    __nv_bfloat16 h1 = __float2bfloat16(v.y);
    __nv_bfloat16 h2 = __float2bfloat16(v.z);
    __nv_bfloat16 h3 = __float2bfloat16(v.w);
    __nv_bfloat16 l0 = __float2bfloat16(v.x - __bfloat162float(h0));
    __nv_bfloat16 l1 = __float2bfloat16(v.y - __bfloat162float(h1));
    __nv_bfloat16 l2 = __float2bfloat16(v.z - __bfloat162float(h2));
    __nv_bfloat16 l3 = __float2bfloat16(v.w - __bfloat162float(h3));
    __nv_bfloat162* hp = (__nv_bfloat162*)hi;
    __nv_bfloat162* lp = (__nv_bfloat162*)lo;
    hp[2 * i]     = __nv_bfloat162(h0, h1);
    hp[2 * i + 1] = __nv_bfloat162(h2, h3);
    lp[2 * i]     = __nv_bfloat162(l0, l1);
    lp[2 * i + 1] = __nv_bfloat162(l2, l3);
}

// ======================= mma.sync bf16x3 GEMM =============================
// C[M][N] = (Ah+Al)[M][K] * (Wh+Wl)[N][K]^T + bias, fp32 accumulate.
// Block tile 128x128, K-chunk 64, double-buffered cp.async stages.
// 8 warps: warp grid 4(M) x 2(N), warp tile 32x64, mma.m16n8k16.
#define GK 2048
#define GBK 64
#define NCHUNK (GK / GBK)
#define TILE_BYTES 16384            // 128 rows * 128B (64 bf16)
#define STAGE_BYTES (4 * TILE_BYTES)

__global__ __launch_bounds__(256, 1) void gemm_bf16x3(
    const __nv_bfloat16* __restrict__ Ah, const __nv_bfloat16* __restrict__ Al,
    const __nv_bfloat16* __restrict__ Wh, const __nv_bfloat16* __restrict__ Wl,
    const float* __restrict__ bias, float* __restrict__ C, int Ndim)
{
    extern __shared__ char smem_raw[];
    char* tiles = (char*)(((uintptr_t)smem_raw + 1023) & ~(uintptr_t)1023);
    const uint32_t tiles_u32 = smem_u32(tiles);

    const int tid  = threadIdx.x;
    const int wid  = tid >> 5;
    const int lane = tid & 31;
    const int bm = blockIdx.y * 128;
    const int bn = blockIdx.x * 128;
    const int wm = (wid & 3) * 32;     // warp M offset in block tile
    const int wn = (wid >> 2) * 64;    // warp N offset in block tile

    const __nv_bfloat16* srcs[4] = {Ah, Al, Wh, Wl};

    // ---- async load one K-chunk into stage s (swizzled) ----
    auto load_chunk = [&](int k0, int s) {
        const uint32_t sb = tiles_u32 + s * STAGE_BYTES;
#pragma unroll
        for (int j = 0; j < 16; j++) {
            int e = tid + j * 256;
            int t = e >> 10;                 // tile 0..3 (Ah,Al,Wh,Wl)
            int r = (e >> 3) & 127;          // row in tile
            int c = (e & 7) * 8;             // bf16 col (0..56 step 8)
            int row = (t < 2 ? bm : bn) + r;
            const void* src = &srcs[t][(size_t)row * GK + k0 + c];
            uint32_t dst = sb + t * TILE_BYTES + SWZ128((uint32_t)(r * 128 + c * 2));
            cp_async16(dst, src);
        }
    };

    float c[2][8][4];
#pragma unroll
    for (int mt = 0; mt < 2; mt++)
#pragma unroll
        for (int nt = 0; nt < 8; nt++)
#pragma unroll
            for (int q = 0; q < 4; q++) c[mt][nt][q] = 0.f;

    const int mi = lane >> 3, rr = lane & 7;

    load_chunk(0, 0);
    CP_COMMIT();

    for (int i = 0; i < NCHUNK; i++) {
        const int s = i & 1;
        if (i + 1 < NCHUNK) {
            load_chunk((i + 1) * GBK, s ^ 1);
            CP_COMMIT();
            CP_WAIT(1);
        } else {
            CP_WAIT(0);
        }
        __syncthreads();

        const uint32_t st   = tiles_u32 + s * STAGE_BYTES;
        const uint32_t Ah_b = st;
        const uint32_t Al_b = st + TILE_BYTES;
        const uint32_t Wh_b = st + 2 * TILE_BYTES;
        const uint32_t Wl_b = st + 3 * TILE_BYTES;

#pragma unroll
        for (int k16 = 0; k16 < 4; k16++) {
            const int kb = k16 * 16;
            uint32_t ah[2][4], al[2][4], bh[4][4], bl[4][4];
#pragma unroll
            for (int mt = 0; mt < 2; mt++) {
                const int m = wm + mt * 16 + (mi & 1) * 8 + rr;
                const int k = kb + (mi >> 1) * 8;
                const uint32_t off = SWZ128((uint32_t)(m * 128 + k * 2));
                ldsm4(Ah_b + off, ah[mt]);
                ldsm4(Al_b + off, al[mt]);
            }
#pragma unroll
            for (int np = 0; np < 4; np++) {
                const int n = wn + np * 16 + (mi >> 1) * 8 + rr;
                const int k = kb + (mi & 1) * 8;
                const uint32_t off = SWZ128((uint32_t)(n * 128 + k * 2));
                ldsm4(Wh_b + off, bh[np]);
                ldsm4(Wl_b + off, bl[np]);
            }
#pragma unroll
            for (int mt = 0; mt < 2; mt++)
#pragma unroll
                for (int nt = 0; nt < 8; nt++) {
                    const uint32_t* bhp = &bh[nt >> 1][(nt & 1) * 2];
                    const uint32_t* blp = &bl[nt >> 1][(nt & 1) * 2];
                    mma_bf16(c[mt][nt], ah[mt], bhp);
                    mma_bf16(c[mt][nt], ah[mt], blp);
                    mma_bf16(c[mt][nt], al[mt], bhp);
                }
        }
        __syncthreads();
    }

    // epilogue: add bias, store fp32
#pragma unroll
    for (int mt = 0; mt < 2; mt++) {
        const int row0 = bm + wm + mt * 16 + (lane >> 2);
#pragma unroll
        for (int nt = 0; nt < 8; nt++) {
            const int col = bn + wn + nt * 8 + (lane & 3) * 2;
            const float b0 = bias[col], b1 = bias[col + 1];
            float2 v0 = make_float2(c[mt][nt][0] + b0, c[mt][nt][1] + b1);
            float2 v1 = make_float2(c[mt][nt][2] + b0, c[mt][nt][3] + b1);
            *(float2*)&C[(size_t)row0 * Ndim + col]       = v0;
            *(float2*)&C[(size_t)(row0 + 8) * Ndim + col] = v1;
        }
    }
}

// ======================= RoPE + split =====================================
__global__ __launch_bounds__(256) void rope_split(
    const float* __restrict__ cosb, const float* __restrict__ sinb,
    float* __restrict__ Q, const float* __restrict__ KV,
    float* __restrict__ K, float* __restrict__ V)
{
    const int tok = blockIdx.x;
    const int tid = threadIdx.x;
    const float* c = cosb + (size_t)tok * HD;
    const float* s = sinb + (size_t)tok * HD;

    for (int p = tid; p < H * 64; p += 256) {
        const int h = p >> 6, d = p & 63;
        const size_t base = (size_t)tok * D + h * HD;
        const float a = Q[base + d], b2 = Q[base + d + 64];
        Q[base + d]      = a  * c[d]      - b2 * s[d];
        Q[base + d + 64] = b2 * c[d + 64] + a  * s[d + 64];
    }
    for (int p = tid; p < HKV * 64; p += 256) {
        const int h = p >> 6, d = p & 63;
        const size_t ib = (size_t)tok * KVDIM + h * HD;
        const size_t ob = (size_t)tok * KDIM  + h * HD;
        const float a = KV[ib + d], b2 = KV[ib + d + 64];
        K[ob + d]      = a  * c[d]      - b2 * s[d];
        K[ob + d + 64] = b2 * c[d + 64] + a  * s[d + 64];
    }
    for (int e = tid; e < KDIM; e += 256)
        V[(size_t)tok * KDIM + e] = KV[(size_t)tok * KVDIM + KDIM + e];
}

// ======================= flash attention (fp32) ===========================
#define FA_BM 64
#define FA_BN 32
#define FA_PAD 132

__global__ __launch_bounds__(256) void flash_attn(
    const float* __restrict__ Q, const float* __restrict__ K,
    const float* __restrict__ V, float* __restrict__ O)
{
    extern __shared__ float smem[];
    float* Qs = smem;
    float* Ks = Qs + FA_BM * FA_PAD;
    float* Vs = Ks + FA_BN * FA_PAD;

    const int tid  = threadIdx.x;
    const int w    = tid >> 5;
    const int lane = tid & 31;
    const int m0   = blockIdx.x * FA_BM;
    const int bh   = blockIdx.y;
    const int b    = bh / H;
    const int h    = bh % H;
    const int kvh  = h / GROUPS;
    const float scale = 0.08838834764831845f;

    {
        const int f = tid & 31, r0 = tid >> 5;
#pragma unroll
        for (int i = 0; i < 8; i++) {
            const int row = r0 + i * 8;
            const size_t g = (((size_t)(b * L + m0 + row)) * H + h) * HD + f * 4;
            *(float4*)&Qs[row * FA_PAD + f * 4] = *(const float4*)&Q[g];
        }
    }
    __syncthreads();

    float4 o4[8];
    float m_r[8], l_r[8];
#pragma unroll
    for (int r = 0; r < 8; r++) {
        o4[r] = make_float4(0.f, 0.f, 0.f, 0.f);
        m_r[r] = -INFINITY;
        l_r[r] = 0.f;
    }

    const int ntiles = (m0 + FA_BM) / FA_BN;
    for (int t = 0; t < ntiles; t++) {
        const int n0 = t * FA_BN;
        {
            const int f = tid & 31, r0 = tid >> 5;
#pragma unroll
            for (int i = 0; i < 4; i++) {
                const int kr = r0 + i * 8;
                const size_t g = (((size_t)(b * L + n0 + kr)) * HKV + kvh) * HD + f * 4;
                *(float4*)&Ks[kr * FA_PAD + f * 4] = *(const float4*)&K[g];
                *(float4*)&Vs[kr * FA_PAD + f * 4] = *(const float4*)&V[g];
            }
        }
        __syncthreads();

        float s[8];
#pragma unroll
        for (int r = 0; r < 8; r++) s[r] = 0.f;
#pragma unroll
        for (int d4 = 0; d4 < 32; d4++) {
            float4 k4 = *(const float4*)&Ks[lane * FA_PAD + d4 * 4];
#pragma unroll
            for (int r = 0; r < 8; r++) {
                float4 q4 = *(const float4*)&Qs[(w * 8 + r) * FA_PAD + d4 * 4];
                s[r] = fmaf(q4.x, k4.x, s[r]);
                s[r] = fmaf(q4.y, k4.y, s[r]);
                s[r] = fmaf(q4.z, k4.z, s[r]);
                s[r] = fmaf(q4.w, k4.w, s[r]);
            }
        }

        const int keyg = n0 + lane;
        float p[8];
#pragma unroll
        for (int r = 0; r < 8; r++) {
            const int qg = m0 + w * 8 + r;
            float sv = (keyg <= qg) ? s[r] * scale : -INFINITY;
            float mx = sv;
#pragma unroll
            for (int off = 16; off; off >>= 1)
                mx = fmaxf(mx, __shfl_xor_sync(0xffffffffu, mx, off));
            const float m_new = fmaxf(m_r[r], mx);
            float pv = __expf(sv - m_new);
            float ps = pv;
#pragma unroll
            for (int off = 16; off; off >>= 1)
                ps += __shfl_xor_sync(0xffffffffu, ps, off);
            const float alpha = __expf(m_r[r] - m_new);
            l_r[r] = l_r[r] * alpha + ps;
            m_r[r] = m_new;
            o4[r].x *= alpha; o4[r].y *= alpha; o4[r].z *= alpha; o4[r].w *= alpha;
            p[r] = pv;
        }

#pragma unroll
        for (int key = 0; key < FA_BN; key++) {
            float4 v4 = *(const float4*)&Vs[key * FA_PAD + lane * 4];
#pragma unroll
            for (int r = 0; r < 8; r++) {
                const float pk = __shfl_sync(0xffffffffu, p[r], key);
                o4[r].x = fmaf(pk, v4.x, o4[r].x);
                o4[r].y = fmaf(pk, v4.y, o4[r].y);
                o4[r].z = fmaf(pk, v4.z, o4[r].z);
                o4[r].w = fmaf(pk, v4.w, o4[r].w);
            }
        }
        __syncthreads();
    }

#pragma unroll
    for (int r = 0; r < 8; r++) {
        const int qg = m0 + w * 8 + r;
        const float inv = 1.f / l_r[r];
        float4 o = make_float4(o4[r].x * inv, o4[r].y * inv,
                               o4[r].z * inv, o4[r].w * inv);
        *(float4*)&O[(((size_t)(b * L + qg)) * H + h) * HD + lane * 4] = o;
    }
}

// ===========================================================================
extern "C" void kernel_launch(void* const* d_in, const int* in_sizes, int n_in,
                              void* d_out, int out_size)
{
    (void)in_sizes; (void)n_in; (void)out_size;
    const float* x    = (const float*)d_in[0];
    const float* cosb = (const float*)d_in[1];
    const float* sinb = (const float*)d_in[2];
    const float* Wq   = (const float*)d_in[3];
    const float* bq   = (const float*)d_in[4];
    const float* Wkv  = (const float*)d_in[5];
    const float* bkv  = (const float*)d_in[6];
    const float* Wo   = (const float*)d_in[7];
    const float* bo   = (const float*)d_in[8];
    float* out = (float*)d_out;

    float *Qb, *KVb, *Kb, *Vb, *Ab;
    __nv_bfloat16 *xh, *xl, *wh, *wl;
    cudaGetSymbolAddress((void**)&Qb,  g_Q);
    cudaGetSymbolAddress((void**)&KVb, g_KV);
    cudaGetSymbolAddress((void**)&Kb,  g_K);
    cudaGetSymbolAddress((void**)&Vb,  g_V);
    cudaGetSymbolAddress((void**)&Ab,  g_A);
    cudaGetSymbolAddress((void**)&xh,  g_xh);
    cudaGetSymbolAddress((void**)&xl,  g_xl);
    cudaGetSymbolAddress((void**)&wh,  g_wh);
    cudaGetSymbolAddress((void**)&wl,  g_wl);

    const int gemm_smem = 1024 + 2 * STAGE_BYTES;
    cudaFuncSetAttribute(gemm_bf16x3, cudaFuncAttributeMaxDynamicSharedMemorySize,
                         gemm_smem);

    // convert x and Wq to hi/lo bf16
    {
        int n4 = (M_TOK * D) / 4;
        cvt_hilo<<<(n4 + 255) / 256, 256>>>(x, xh, xl, n4);
        int w4 = (D * D) / 4;
        cvt_hilo<<<(w4 + 255) / 256, 256>>>(Wq, wh, wl, w4);
    }
    // Q projection
    gemm_bf16x3<<<dim3(D / 128, M_TOK / 128), 256, gemm_smem>>>(
        xh, xl, wh, wl, bq, Qb, D);

    // KV projection
    {
        int w4 = (KVDIM * D) / 4;
        cvt_hilo<<<(w4 + 255) / 256, 256>>>(Wkv, wh, wl, w4);
    }
    gemm_bf16x3<<<dim3(KVDIM / 128, M_TOK / 128), 256, gemm_smem>>>(
        xh, xl, wh, wl, bkv, KVb, KVDIM);

    // RoPE + split
    rope_split<<<M_TOK, 256>>>(cosb, sinb, Qb, KVb, Kb, Vb);

    // Flash attention
    size_t fa_smem = (size_t)(FA_BM * FA_PAD + 2 * FA_BN * FA_PAD) * sizeof(float);
    cudaFuncSetAttribute(flash_attn, cudaFuncAttributeMaxDynamicSharedMemorySize,
                         (int)fa_smem);
    flash_attn<<<dim3(L / FA_BM, B * H), 256, fa_smem>>>(Qb, Kb, Vb, Ab);

    // O projection
    {
        int n4 = (M_TOK * D) / 4;
        cvt_hilo<<<(n4 + 255) / 256, 256>>>(Ab, xh, xl, n4);
        int w4 = (D * D) / 4;
        cvt_hilo<<<(w4 + 255) / 256, 256>>>(Wo, wh, wl, w4);
    }
    gemm_bf16x3<<<dim3(D / 128, M_TOK / 128), 256, gemm_smem>>>(
        xh, xl, wh, wl, bo, out, D);
}

// round 7
// speedup vs baseline: 3.3562x; 1.9599x over previous
#include <cuda_runtime.h>
#include <cuda_bf16.h>
#include <math.h>
#include <stdint.h>

#define B 2
#define L 2048
#define D 2048
#define H 16
#define HKV 4
#define HD 128
#define GROUPS (H / HKV)
#define M_TOK (B * L)          // 4096 tokens
#define KVDIM (2 * HKV * HD)   // 1024
#define KDIM  (HKV * HD)       // 512
#define SCALE 0.08838834764831845f

// ---------------- scratch (static device arrays) ---------------------------
__device__ float g_Q [(size_t)M_TOK * D];      // Q proj out (fp32)
__device__ float g_KV[(size_t)M_TOK * KVDIM];  // KV proj out (fp32)
__device__ __nv_bfloat16 g_xh[(size_t)M_TOK * D];
__device__ __nv_bfloat16 g_xl[(size_t)M_TOK * D];
__device__ __nv_bfloat16 g_wh[(size_t)D * D];
__device__ __nv_bfloat16 g_wl[(size_t)D * D];
__device__ __nv_bfloat16 g_qh[(size_t)M_TOK * D];     // roped+scaled Q hi/lo
__device__ __nv_bfloat16 g_ql[(size_t)M_TOK * D];
__device__ __nv_bfloat16 g_kh[(size_t)M_TOK * KDIM];
__device__ __nv_bfloat16 g_kl[(size_t)M_TOK * KDIM];
__device__ __nv_bfloat16 g_vh[(size_t)M_TOK * KDIM];
__device__ __nv_bfloat16 g_vl[(size_t)M_TOK * KDIM];
__device__ __nv_bfloat16 g_ah[(size_t)M_TOK * D];     // attn out hi/lo
__device__ __nv_bfloat16 g_al[(size_t)M_TOK * D];

// ======================= helpers ==========================================
__device__ __forceinline__ uint32_t smem_u32(const void* p) {
    uint32_t a;
    asm("{ .reg .u64 t; cvta.to.shared.u64 t, %1; cvt.u32.u64 %0, t; }"
        : "=r"(a) : "l"(p));
    return a;
}
#define SWZ128(off) ((off) ^ (((off) >> 3) & 0x70))

__device__ __forceinline__ void ldsm4(uint32_t addr, uint32_t* r) {
    asm volatile("ldmatrix.sync.aligned.m8n8.x4.shared.b16 {%0,%1,%2,%3}, [%4];"
                 : "=r"(r[0]), "=r"(r[1]), "=r"(r[2]), "=r"(r[3]) : "r"(addr));
}
__device__ __forceinline__ void ldsm2(uint32_t addr, uint32_t* r) {
    asm volatile("ldmatrix.sync.aligned.m8n8.x2.shared.b16 {%0,%1}, [%2];"
                 : "=r"(r[0]), "=r"(r[1]) : "r"(addr));
}
__device__ __forceinline__ void ldsm2t(uint32_t addr, uint32_t* r) {
    asm volatile("ldmatrix.sync.aligned.m8n8.x2.trans.shared.b16 {%0,%1}, [%2];"
                 : "=r"(r[0]), "=r"(r[1]) : "r"(addr));
}
__device__ __forceinline__ void mma_bf16(float* c, const uint32_t* a,
                                         const uint32_t* b) {
    asm volatile(
        "mma.sync.aligned.m16n8k16.row.col.f32.bf16.bf16.f32 "
        "{%0,%1,%2,%3}, {%4,%5,%6,%7}, {%8,%9}, {%0,%1,%2,%3};"
        : "+f"(c[0]), "+f"(c[1]), "+f"(c[2]), "+f"(c[3])
        : "r"(a[0]), "r"(a[1]), "r"(a[2]), "r"(a[3]), "r"(b[0]), "r"(b[1]));
}
__device__ __forceinline__ void cp_async16(uint32_t dst, const void* src) {
    asm volatile("cp.async.cg.shared.global [%0], [%1], 16;"
                 :: "r"(dst), "l"(src));
}
#define CP_COMMIT() asm volatile("cp.async.commit_group;" ::: "memory")
#define CP_WAIT(N)  asm volatile("cp.async.wait_group %0;" :: "n"(N) : "memory")

// pack (lo, hi) floats -> bf16x2 register (lo in low 16 bits)
__device__ __forceinline__ uint32_t pack_bf16x2(float lo, float hi) {
    uint32_t r;
    asm("cvt.rn.bf16x2.f32 %0, %1, %2;" : "=r"(r) : "f"(hi), "f"(lo));
    return r;
}
__device__ __forceinline__ float bf16_round(float x) {
    return __bfloat162float(__float2bfloat16(x));
}

// ======================= hi/lo split conversion ===========================
__global__ __launch_bounds__(256) void cvt_hilo(
    const float* __restrict__ src,
    __nv_bfloat16* __restrict__ hi, __nv_bfloat16* __restrict__ lo, int n4)
{
    int i = blockIdx.x * blockDim.x + threadIdx.x;
    if (i >= n4) return;
    float4 v = ((const float4*)src)[i];
    __nv_bfloat16 h0 = __float2bfloat16(v.x);
    __nv_bfloat16 h1 = __float2bfloat16(v.y);
    __nv_bfloat16 h2 = __float2bfloat16(v.z);
    __nv_bfloat16 h3 = __float2bfloat16(v.w);
    __nv_bfloat16 l0 = __float2bfloat16(v.x - __bfloat162float(h0));
    __nv_bfloat16 l1 = __float2bfloat16(v.y - __bfloat162float(h1));
    __nv_bfloat16 l2 = __float2bfloat16(v.z - __bfloat162float(h2));
    __nv_bfloat16 l3 = __float2bfloat16(v.w - __bfloat162float(h3));
    __nv_bfloat162* hp = (__nv_bfloat162*)hi;
    __nv_bfloat162* lp = (__nv_bfloat162*)lo;
    hp[2 * i]     = __nv_bfloat162(h0, h1);
    hp[2 * i + 1] = __nv_bfloat162(h2, h3);
    lp[2 * i]     = __nv_bfloat162(l0, l1);
    lp[2 * i + 1] = __nv_bfloat162(l2, l3);
}

// ======================= mma.sync bf16x3 GEMM (3-stage pipeline) ==========
#define GK 2048
#define GBK 64
#define NCHUNK (GK / GBK)           // 32
#define TILE_BYTES 16384            // 128 rows * 128B (64 bf16)
#define STAGE_BYTES (4 * TILE_BYTES)

__global__ __launch_bounds__(256, 1) void gemm_bf16x3(
    const __nv_bfloat16* __restrict__ Ah, const __nv_bfloat16* __restrict__ Al,
    const __nv_bfloat16* __restrict__ Wh, const __nv_bfloat16* __restrict__ Wl,
    const float* __restrict__ bias, float* __restrict__ C, int Ndim)
{
    extern __shared__ char smem_raw[];
    char* tiles = (char*)(((uintptr_t)smem_raw + 1023) & ~(uintptr_t)1023);
    const uint32_t tiles_u32 = smem_u32(tiles);

    const int tid  = threadIdx.x;
    const int wid  = tid >> 5;
    const int lane = tid & 31;
    const int bm = blockIdx.y * 128;
    const int bn = blockIdx.x * 128;
    const int wm = (wid & 3) * 32;
    const int wn = (wid >> 2) * 64;

    const __nv_bfloat16* srcs[4] = {Ah, Al, Wh, Wl};

    auto load_chunk = [&](int k0, int s) {
        const uint32_t sb = tiles_u32 + s * STAGE_BYTES;
#pragma unroll
        for (int j = 0; j < 16; j++) {
            int e = tid + j * 256;
            int t = e >> 10;
            int r = (e >> 3) & 127;
            int c = (e & 7) * 8;
            int row = (t < 2 ? bm : bn) + r;
            const void* src = &srcs[t][(size_t)row * GK + k0 + c];
            uint32_t dst = sb + t * TILE_BYTES + SWZ128((uint32_t)(r * 128 + c * 2));
            cp_async16(dst, src);
        }
    };

    float c[2][8][4];
#pragma unroll
    for (int mt = 0; mt < 2; mt++)
#pragma unroll
        for (int nt = 0; nt < 8; nt++)
#pragma unroll
            for (int q = 0; q < 4; q++) c[mt][nt][q] = 0.f;

    const int mi = lane >> 3, rr = lane & 7;

    load_chunk(0, 0);          CP_COMMIT();
    load_chunk(GBK, 1);        CP_COMMIT();

    for (int i = 0; i < NCHUNK; i++) {
        CP_WAIT(1);
        __syncthreads();
        if (i + 2 < NCHUNK) load_chunk((i + 2) * GBK, (i + 2) % 3);
        CP_COMMIT();

        const uint32_t st   = tiles_u32 + (i % 3) * STAGE_BYTES;
        const uint32_t Ah_b = st;
        const uint32_t Al_b = st + TILE_BYTES;
        const uint32_t Wh_b = st + 2 * TILE_BYTES;
        const uint32_t Wl_b = st + 3 * TILE_BYTES;

#pragma unroll
        for (int k16 = 0; k16 < 4; k16++) {
            const int kb = k16 * 16;
            uint32_t ah[2][4], al[2][4], bh[4][4], bl[4][4];
#pragma unroll
            for (int mt = 0; mt < 2; mt++) {
                const int m = wm + mt * 16 + (mi & 1) * 8 + rr;
                const int k = kb + (mi >> 1) * 8;
                const uint32_t off = SWZ128((uint32_t)(m * 128 + k * 2));
                ldsm4(Ah_b + off, ah[mt]);
                ldsm4(Al_b + off, al[mt]);
            }
#pragma unroll
            for (int np = 0; np < 4; np++) {
                const int n = wn + np * 16 + (mi >> 1) * 8 + rr;
                const int k = kb + (mi & 1) * 8;
                const uint32_t off = SWZ128((uint32_t)(n * 128 + k * 2));
                ldsm4(Wh_b + off, bh[np]);
                ldsm4(Wl_b + off, bl[np]);
            }
#pragma unroll
            for (int mt = 0; mt < 2; mt++)
#pragma unroll
                for (int nt = 0; nt < 8; nt++) {
                    const uint32_t* bhp = &bh[nt >> 1][(nt & 1) * 2];
                    const uint32_t* blp = &bl[nt >> 1][(nt & 1) * 2];
                    mma_bf16(c[mt][nt], ah[mt], bhp);
                    mma_bf16(c[mt][nt], ah[mt], blp);
                    mma_bf16(c[mt][nt], al[mt], bhp);
                }
        }
    }

#pragma unroll
    for (int mt = 0; mt < 2; mt++) {
        const int row0 = bm + wm + mt * 16 + (lane >> 2);
#pragma unroll
        for (int nt = 0; nt < 8; nt++) {
            const int col = bn + wn + nt * 8 + (lane & 3) * 2;
            const float b0 = bias[col], b1 = bias[col + 1];
            float2 v0 = make_float2(c[mt][nt][0] + b0, c[mt][nt][1] + b1);
            float2 v1 = make_float2(c[mt][nt][2] + b0, c[mt][nt][3] + b1);
            *(float2*)&C[(size_t)row0 * Ndim + col]       = v0;
            *(float2*)&C[(size_t)(row0 + 8) * Ndim + col] = v1;
        }
    }
}

// ======================= RoPE + split to bf16 hi/lo =======================
__global__ __launch_bounds__(256) void rope_split_cvt(
    const float* __restrict__ cosb, const float* __restrict__ sinb,
    const float* __restrict__ Q, const float* __restrict__ KV,
    __nv_bfloat16* __restrict__ qh, __nv_bfloat16* __restrict__ ql,
    __nv_bfloat16* __restrict__ kh, __nv_bfloat16* __restrict__ kl,
    __nv_bfloat16* __restrict__ vh, __nv_bfloat16* __restrict__ vl)
{
    const int tok = blockIdx.x;
    const int tid = threadIdx.x;
    const float* c = cosb + (size_t)tok * HD;
    const float* s = sinb + (size_t)tok * HD;

    // Q: rope + scale + split
    for (int p = tid; p < H * 64; p += 256) {
        const int h = p >> 6, d = p & 63;
        const size_t base = (size_t)tok * D + h * HD;
        const float a = Q[base + d], b2 = Q[base + d + 64];
        const float e0 = (a  * c[d]      - b2 * s[d])      * SCALE;
        const float e1 = (b2 * c[d + 64] + a  * s[d + 64]) * SCALE;
        const float h0 = bf16_round(e0), h1 = bf16_round(e1);
        qh[base + d]      = __float2bfloat16(h0);
        qh[base + d + 64] = __float2bfloat16(h1);
        ql[base + d]      = __float2bfloat16(e0 - h0);
        ql[base + d + 64] = __float2bfloat16(e1 - h1);
    }
    // K: rope + split
    for (int p = tid; p < HKV * 64; p += 256) {
        const int h = p >> 6, d = p & 63;
        const size_t ib = (size_t)tok * KVDIM + h * HD;
        const size_t ob = (size_t)tok * KDIM  + h * HD;
        const float a = KV[ib + d], b2 = KV[ib + d + 64];
        const float e0 = a  * c[d]      - b2 * s[d];
        const float e1 = b2 * c[d + 64] + a  * s[d + 64];
        const float h0 = bf16_round(e0), h1 = bf16_round(e1);
        kh[ob + d]      = __float2bfloat16(h0);
        kh[ob + d + 64] = __float2bfloat16(h1);
        kl[ob + d]      = __float2bfloat16(e0 - h0);
        kl[ob + d + 64] = __float2bfloat16(e1 - h1);
    }
    // V: split
    for (int e = tid; e < KDIM; e += 256) {
        const float v = KV[(size_t)tok * KVDIM + KDIM + e];
        const float h0 = bf16_round(v);
        vh[(size_t)tok * KDIM + e] = __float2bfloat16(h0);
        vl[(size_t)tok * KDIM + e] = __float2bfloat16(v - h0);
    }
}

// ======================= flash attention (tensor cores, bf16x3) ===========
// BM=128 (8 warps x 16 rows), BN=64 keys/tile, HD=128.
// K/V tiles in smem, 272B row pitch (odd*16B -> conflict-free ldmatrix).
#define FBM 128
#define FBN 64
#define KP  136                       // bf16 per row (pitch)
#define KT_BYTES (FBN * KP * 2)       // 17408
#define FSTG (4 * KT_BYTES)           // Kh,Kl,Vh,Vl per stage

__global__ __launch_bounds__(256, 1) void flash_mma(
    const __nv_bfloat16* __restrict__ Qh, const __nv_bfloat16* __restrict__ Ql,
    const __nv_bfloat16* __restrict__ Kh, const __nv_bfloat16* __restrict__ Kl,
    const __nv_bfloat16* __restrict__ Vh, const __nv_bfloat16* __restrict__ Vl,
    __nv_bfloat16* __restrict__ Ah, __nv_bfloat16* __restrict__ Al)
{
    extern __shared__ char smem_raw[];
    const uint32_t smem = smem_u32(smem_raw);

    const int tid  = threadIdx.x;
    const int w    = tid >> 5;
    const int lane = tid & 31;
    const int m0   = blockIdx.x * FBM;
    const int bh   = blockIdx.y;
    const int b    = bh / H;
    const int h    = bh % H;
    const int kvh  = h / GROUPS;

    const int rowg0 = m0 + w * 16 + (lane >> 2);     // this thread's row (c0,c1)
    const int rowg1 = rowg0 + 8;                     // row for (c2,c3)

    // ---- Q fragments from global (b,l,h,d layout) ----
    uint32_t qh[8][4], ql[8][4];
    {
        const size_t base0 = ((size_t)(b * L + rowg0) * H + h) * HD;
        const size_t base1 = base0 + (size_t)8 * H * HD;
#pragma unroll
        for (int j = 0; j < 8; j++) {
            const int c0 = j * 16 + (lane & 3) * 2;
            qh[j][0] = *(const uint32_t*)&Qh[base0 + c0];
            qh[j][1] = *(const uint32_t*)&Qh[base1 + c0];
            qh[j][2] = *(const uint32_t*)&Qh[base0 + c0 + 8];
            qh[j][3] = *(const uint32_t*)&Qh[base1 + c0 + 8];
            ql[j][0] = *(const uint32_t*)&Ql[base0 + c0];
            ql[j][1] = *(const uint32_t*)&Ql[base1 + c0];
            ql[j][2] = *(const uint32_t*)&Ql[base0 + c0 + 8];
            ql[j][3] = *(const uint32_t*)&Ql[base1 + c0 + 8];
        }
    }

    const __nv_bfloat16* kvsrc[4] = {Kh, Kl, Vh, Vl};
    auto load_kv = [&](int t, int s) {
        const int n0 = t * FBN;
        const uint32_t sb = smem + s * FSTG;
#pragma unroll
        for (int jj = 0; jj < 16; jj++) {
            int e = tid + jj * 256;
            int buf = e >> 10;
            int r   = (e >> 4) & 63;
            int ch  = e & 15;
            const void* src =
                &kvsrc[buf][((size_t)(b * L + n0 + r) * HKV + kvh) * HD + ch * 8];
            uint32_t dst = sb + buf * KT_BYTES + (uint32_t)(r * KP + ch * 8) * 2;
            cp_async16(dst, src);
        }
    };

    float o[16][4];
#pragma unroll
    for (int nt = 0; nt < 16; nt++)
#pragma unroll
        for (int q = 0; q < 4; q++) o[nt][q] = 0.f;
    float mrow0 = -1e30f, mrow1 = -1e30f, lrow0 = 0.f, lrow1 = 0.f;

    const int ntiles = m0 / FBN + 2;
    load_kv(0, 0);
    CP_COMMIT();

    for (int t = 0; t < ntiles; t++) {
        CP_WAIT(0);
        __syncthreads();
        if (t + 1 < ntiles) load_kv(t + 1, (t + 1) & 1);
        CP_COMMIT();

        const int n0 = t * FBN;
        // warp fully above diagonal? (all keys > all of warp's rows)
        if (n0 > m0 + w * 16 + 15) continue;

        const uint32_t st  = smem + (t & 1) * FSTG;
        const uint32_t Khs = st;
        const uint32_t Kls = st + KT_BYTES;
        const uint32_t Vhs = st + 2 * KT_BYTES;
        const uint32_t Vls = st + 3 * KT_BYTES;

        // ---- scores ----
        float s8[8][4];
#pragma unroll
        for (int nt = 0; nt < 8; nt++)
#pragma unroll
            for (int q = 0; q < 4; q++) s8[nt][q] = 0.f;

        const int rlane = lane & 7;
        const int khalf = (lane >> 3) & 1;
#pragma unroll
        for (int j = 0; j < 8; j++) {
#pragma unroll
            for (int nt = 0; nt < 8; nt++) {
                uint32_t kb2[2], kl2[2];
                const uint32_t a =
                    (uint32_t)((nt * 8 + rlane) * KP + j * 16 + khalf * 8) * 2;
                ldsm2(Khs + a, kb2);
                ldsm2(Kls + a, kl2);
                mma_bf16(s8[nt], qh[j], kb2);
                mma_bf16(s8[nt], qh[j], kl2);
                mma_bf16(s8[nt], ql[j], kb2);
            }
        }

        // ---- causal mask (only needed near diagonal) ----
        if (t >= ntiles - 2) {
            const int colc = n0 + (lane & 3) * 2;
#pragma unroll
            for (int nt = 0; nt < 8; nt++) {
                const int cg = colc + nt * 8;
                if (cg     > rowg0) s8[nt][0] = -1e30f;
                if (cg + 1 > rowg0) s8[nt][1] = -1e30f;
                if (cg     > rowg1) s8[nt][2] = -1e30f;
                if (cg + 1 > rowg1) s8[nt][3] = -1e30f;
            }
        }

        // ---- online softmax ----
        float mx0 = -1e30f, mx1 = -1e30f;
#pragma unroll
        for (int nt = 0; nt < 8; nt++) {
            mx0 = fmaxf(mx0, fmaxf(s8[nt][0], s8[nt][1]));
            mx1 = fmaxf(mx1, fmaxf(s8[nt][2], s8[nt][3]));
        }
        mx0 = fmaxf(mx0, __shfl_xor_sync(0xffffffffu, mx0, 1));
        mx0 = fmaxf(mx0, __shfl_xor_sync(0xffffffffu, mx0, 2));
        mx1 = fmaxf(mx1, __shfl_xor_sync(0xffffffffu, mx1, 1));
        mx1 = fmaxf(mx1, __shfl_xor_sync(0xffffffffu, mx1, 2));

        const float mn0 = fmaxf(mrow0, mx0);
        const float mn1 = fmaxf(mrow1, mx1);
        const float alpha0 = __expf(mrow0 - mn0);
        const float alpha1 = __expf(mrow1 - mn1);

        float sum0 = 0.f, sum1 = 0.f;
#pragma unroll
        for (int nt = 0; nt < 8; nt++) {
            s8[nt][0] = __expf(s8[nt][0] - mn0);
            s8[nt][1] = __expf(s8[nt][1] - mn0);
            s8[nt][2] = __expf(s8[nt][2] - mn1);
            s8[nt][3] = __expf(s8[nt][3] - mn1);
            sum0 += s8[nt][0] + s8[nt][1];
            sum1 += s8[nt][2] + s8[nt][3];
        }
        sum0 += __shfl_xor_sync(0xffffffffu, sum0, 1);
        sum0 += __shfl_xor_sync(0xffffffffu, sum0, 2);
        sum1 += __shfl_xor_sync(0xffffffffu, sum1, 1);
        sum1 += __shfl_xor_sync(0xffffffffu, sum1, 2);

        lrow0 = lrow0 * alpha0 + sum0;
        lrow1 = lrow1 * alpha1 + sum1;
        mrow0 = mn0; mrow1 = mn1;

#pragma unroll
        for (int nt = 0; nt < 16; nt++) {
            o[nt][0] *= alpha0; o[nt][1] *= alpha0;
            o[nt][2] *= alpha1; o[nt][3] *= alpha1;
        }

        // ---- P·V ----
#pragma unroll
        for (int kt = 0; kt < 4; kt++) {
            // P a-fragments from score tiles 2kt, 2kt+1
            uint32_t ph4[4], pl4[4];
            {
                const float* p0 = s8[2 * kt];
                const float* p1 = s8[2 * kt + 1];
                float h;
                h = bf16_round(p0[0]); float l00 = p0[0] - h;
                h = bf16_round(p0[1]); float l01 = p0[1] - h;
                h = bf16_round(p0[2]); float l02 = p0[2] - h;
                h = bf16_round(p0[3]); float l03 = p0[3] - h;
                ph4[0] = pack_bf16x2(p0[0], p0[1]);
                ph4[1] = pack_bf16x2(p0[2], p0[3]);
                pl4[0] = pack_bf16x2(l00, l01);
                pl4[1] = pack_bf16x2(l02, l03);
                h = bf16_round(p1[0]); float l10 = p1[0] - h;
                h = bf16_round(p1[1]); float l11 = p1[1] - h;
                h = bf16_round(p1[2]); float l12 = p1[2] - h;
                h = bf16_round(p1[3]); float l13 = p1[3] - h;
                ph4[2] = pack_bf16x2(p1[0], p1[1]);
                ph4[3] = pack_bf16x2(p1[2], p1[3]);
                pl4[2] = pack_bf16x2(l10, l11);
                pl4[3] = pack_bf16x2(l12, l13);
            }
#pragma unroll
            for (int nt = 0; nt < 16; nt++) {
                uint32_t vh2[2], vl2[2];
                const uint32_t a =
                    (uint32_t)((kt * 16 + khalf * 8 + rlane) * KP + nt * 8) * 2;
                ldsm2t(Vhs + a, vh2);
                ldsm2t(Vls + a, vl2);
                mma_bf16(o[nt], ph4, vh2);
                mma_bf16(o[nt], ph4, vl2);
                mma_bf16(o[nt], pl4, vh2);
            }
        }
    }

    // ---- epilogue: normalize, split, store (b,l,h,d) ----
    const float inv0 = 1.f / lrow0;
    const float inv1 = 1.f / lrow1;
    const size_t base0 = ((size_t)(b * L + rowg0) * H + h) * HD;
    const size_t base1 = base0 + (size_t)8 * H * HD;
#pragma unroll
    for (int nt = 0; nt < 16; nt++) {
        const int col = nt * 8 + (lane & 3) * 2;
        const float f0 = o[nt][0] * inv0, f1 = o[nt][1] * inv0;
        const float f2 = o[nt][2] * inv1, f3 = o[nt][3] * inv1;
        const float h0 = bf16_round(f0), h1 = bf16_round(f1);
        const float h2 = bf16_round(f2), h3 = bf16_round(f3);
        *(uint32_t*)&Ah[base0 + col] = pack_bf16x2(f0, f1);
        *(uint32_t*)&Ah[base1 + col] = pack_bf16x2(f2, f3);
        *(uint32_t*)&Al[base0 + col] = pack_bf16x2(f0 - h0, f1 - h1);
        *(uint32_t*)&Al[base1 + col] = pack_bf16x2(f2 - h2, f3 - h3);
    }
}

// ===========================================================================
extern "C" void kernel_launch(void* const* d_in, const int* in_sizes, int n_in,
                              void* d_out, int out_size)
{
    (void)in_sizes; (void)n_in; (void)out_size;
    const float* x    = (const float*)d_in[0];
    const float* cosb = (const float*)d_in[1];
    const float* sinb = (const float*)d_in[2];
    const float* Wq   = (const float*)d_in[3];
    const float* bq   = (const float*)d_in[4];
    const float* Wkv  = (const float*)d_in[5];
    const float* bkv  = (const float*)d_in[6];
    const float* Wo   = (const float*)d_in[7];
    const float* bo   = (const float*)d_in[8];
    float* out = (float*)d_out;

    float *Qb, *KVb;
    __nv_bfloat16 *xh, *xl, *wh, *wl, *qh, *ql, *kh, *kl, *vh, *vl, *ah, *al;
    cudaGetSymbolAddress((void**)&Qb,  g_Q);
    cudaGetSymbolAddress((void**)&KVb, g_KV);
    cudaGetSymbolAddress((void**)&xh,  g_xh);
    cudaGetSymbolAddress((void**)&xl,  g_xl);
    cudaGetSymbolAddress((void**)&wh,  g_wh);
    cudaGetSymbolAddress((void**)&wl,  g_wl);
    cudaGetSymbolAddress((void**)&qh,  g_qh);
    cudaGetSymbolAddress((void**)&ql,  g_ql);
    cudaGetSymbolAddress((void**)&kh,  g_kh);
    cudaGetSymbolAddress((void**)&kl,  g_kl);
    cudaGetSymbolAddress((void**)&vh,  g_vh);
    cudaGetSymbolAddress((void**)&vl,  g_vl);
    cudaGetSymbolAddress((void**)&ah,  g_ah);
    cudaGetSymbolAddress((void**)&al,  g_al);

    const int gemm_smem = 1024 + 3 * STAGE_BYTES;
    cudaFuncSetAttribute(gemm_bf16x3, cudaFuncAttributeMaxDynamicSharedMemorySize,
                         gemm_smem);
    const int fa_smem = 2 * FSTG;
    cudaFuncSetAttribute(flash_mma, cudaFuncAttributeMaxDynamicSharedMemorySize,
                         fa_smem);

    // split x and Wq
    {
        int n4 = (M_TOK * D) / 4;
        cvt_hilo<<<(n4 + 255) / 256, 256>>>(x, xh, xl, n4);
        int w4 = (D * D) / 4;
        cvt_hilo<<<(w4 + 255) / 256, 256>>>(Wq, wh, wl, w4);
    }
    gemm_bf16x3<<<dim3(D / 128, M_TOK / 128), 256, gemm_smem>>>(
        xh, xl, wh, wl, bq, Qb, D);

    {
        int w4 = (KVDIM * D) / 4;
        cvt_hilo<<<(w4 + 255) / 256, 256>>>(Wkv, wh, wl, w4);
    }
    gemm_bf16x3<<<dim3(KVDIM / 128, M_TOK / 128), 256, gemm_smem>>>(
        xh, xl, wh, wl, bkv, KVb, KVDIM);

    // RoPE + split to bf16 hi/lo (scale folded into Q)
    rope_split_cvt<<<M_TOK, 256>>>(cosb, sinb, Qb, KVb, qh, ql, kh, kl, vh, vl);

    // tensor-core flash attention -> Ah/Al splits
    flash_mma<<<dim3(L / FBM, B * H), 256, fa_smem>>>(
        qh, ql, kh, kl, vh, vl, ah, al);

    // O projection (reads Ah/Al directly)
    {
        int w4 = (D * D) / 4;
        cvt_hilo<<<(w4 + 255) / 256, 256>>>(Wo, wh, wl, w4);
    }
    gemm_bf16x3<<<dim3(D / 128, M_TOK / 128), 256, gemm_smem>>>(
        ah, al, wh, wl, bo, out, D);
}

// round 8
// speedup vs baseline: 3.3697x; 1.0040x over previous
#include <cuda_runtime.h>
#include <cuda_bf16.h>
#include <math.h>
#include <stdint.h>

#define B 2
#define L 2048
#define D 2048
#define H 16
#define HKV 4
#define HD 128
#define GROUPS (H / HKV)
#define M_TOK (B * L)          // 4096 tokens
#define KVDIM (2 * HKV * HD)   // 1024
#define KDIM  (HKV * HD)       // 512
#define SCALE 0.08838834764831845f

// ---------------- scratch (static device arrays) ---------------------------
__device__ float g_Q [(size_t)M_TOK * D];      // Q proj out (fp32)
__device__ float g_KV[(size_t)M_TOK * KVDIM];  // KV proj out (fp32)
__device__ __nv_bfloat16 g_xh[(size_t)M_TOK * D];
__device__ __nv_bfloat16 g_xl[(size_t)M_TOK * D];
__device__ __nv_bfloat16 g_wqh[(size_t)D * D];
__device__ __nv_bfloat16 g_wql[(size_t)D * D];
__device__ __nv_bfloat16 g_wkh[(size_t)KVDIM * D];
__device__ __nv_bfloat16 g_wkl[(size_t)KVDIM * D];
__device__ __nv_bfloat16 g_woh[(size_t)D * D];
__device__ __nv_bfloat16 g_wol[(size_t)D * D];
__device__ __nv_bfloat16 g_qh[(size_t)M_TOK * D];     // roped+scaled Q hi/lo
__device__ __nv_bfloat16 g_ql[(size_t)M_TOK * D];
__device__ __nv_bfloat16 g_kh[(size_t)M_TOK * KDIM];
__device__ __nv_bfloat16 g_kl[(size_t)M_TOK * KDIM];
__device__ __nv_bfloat16 g_vh[(size_t)M_TOK * KDIM];
__device__ __nv_bfloat16 g_vl[(size_t)M_TOK * KDIM];
__device__ __nv_bfloat16 g_ah[(size_t)M_TOK * D];     // attn out hi/lo
__device__ __nv_bfloat16 g_al[(size_t)M_TOK * D];

// ======================= helpers ==========================================
__device__ __forceinline__ uint32_t smem_u32(const void* p) {
    uint32_t a;
    asm("{ .reg .u64 t; cvta.to.shared.u64 t, %1; cvt.u32.u64 %0, t; }"
        : "=r"(a) : "l"(p));
    return a;
}
#define SWZ128(off) ((off) ^ (((off) >> 3) & 0x70))

__device__ __forceinline__ void ldsm4(uint32_t addr, uint32_t* r) {
    asm volatile("ldmatrix.sync.aligned.m8n8.x4.shared.b16 {%0,%1,%2,%3}, [%4];"
                 : "=r"(r[0]), "=r"(r[1]), "=r"(r[2]), "=r"(r[3]) : "r"(addr));
}
__device__ __forceinline__ void ldsm4t(uint32_t addr, uint32_t* r) {
    asm volatile("ldmatrix.sync.aligned.m8n8.x4.trans.shared.b16 {%0,%1,%2,%3}, [%4];"
                 : "=r"(r[0]), "=r"(r[1]), "=r"(r[2]), "=r"(r[3]) : "r"(addr));
}
__device__ __forceinline__ void mma_bf16(float* c, const uint32_t* a,
                                         const uint32_t* b) {
    asm volatile(
        "mma.sync.aligned.m16n8k16.row.col.f32.bf16.bf16.f32 "
        "{%0,%1,%2,%3}, {%4,%5,%6,%7}, {%8,%9}, {%0,%1,%2,%3};"
        : "+f"(c[0]), "+f"(c[1]), "+f"(c[2]), "+f"(c[3])
        : "r"(a[0]), "r"(a[1]), "r"(a[2]), "r"(a[3]), "r"(b[0]), "r"(b[1]));
}
__device__ __forceinline__ void cp_async16(uint32_t dst, const void* src) {
    asm volatile("cp.async.cg.shared.global [%0], [%1], 16;"
                 :: "r"(dst), "l"(src));
}
#define CP_COMMIT() asm volatile("cp.async.commit_group;" ::: "memory")
#define CP_WAIT(N)  asm volatile("cp.async.wait_group %0;" :: "n"(N) : "memory")

__device__ __forceinline__ uint32_t pack_bf16x2(float lo, float hi) {
    uint32_t r;
    asm("cvt.rn.bf16x2.f32 %0, %1, %2;" : "=r"(r) : "f"(hi), "f"(lo));
    return r;
}
__device__ __forceinline__ float bf16_round(float x) {
    return __bfloat162float(__float2bfloat16(x));
}

// ======================= fused hi/lo split (x + all weights) ==============
#define N4_X   ((M_TOK * D) / 4)          // 2097152
#define N4_WQ  ((D * D) / 4)              // 1048576
#define N4_WKV ((KVDIM * D) / 4)          // 524288
#define N4_WO  ((D * D) / 4)              // 1048576
#define N4_TOT (N4_X + N4_WQ + N4_WKV + N4_WO)

__device__ __forceinline__ void split4(const float* __restrict__ src,
                                       __nv_bfloat16* __restrict__ hi,
                                       __nv_bfloat16* __restrict__ lo, int i) {
    float4 v = ((const float4*)src)[i];
    float h0 = bf16_round(v.x), h1 = bf16_round(v.y);
    float h2 = bf16_round(v.z), h3 = bf16_round(v.w);
    uint32_t* hp = (uint32_t*)hi;
    uint32_t* lp = (uint32_t*)lo;
    hp[2 * i]     = pack_bf16x2(v.x, v.y);
    hp[2 * i + 1] = pack_bf16x2(v.z, v.w);
    lp[2 * i]     = pack_bf16x2(v.x - h0, v.y - h1);
    lp[2 * i + 1] = pack_bf16x2(v.z - h2, v.w - h3);
}

__global__ __launch_bounds__(256) void cvt_all(
    const float* __restrict__ x,  const float* __restrict__ Wq,
    const float* __restrict__ Wkv, const float* __restrict__ Wo,
    __nv_bfloat16* __restrict__ xh,  __nv_bfloat16* __restrict__ xl,
    __nv_bfloat16* __restrict__ wqh, __nv_bfloat16* __restrict__ wql,
    __nv_bfloat16* __restrict__ wkh, __nv_bfloat16* __restrict__ wkl,
    __nv_bfloat16* __restrict__ woh, __nv_bfloat16* __restrict__ wol)
{
    int i = blockIdx.x * blockDim.x + threadIdx.x;
    if (i < N4_X) { split4(x, xh, xl, i); return; }
    i -= N4_X;
    if (i < N4_WQ) { split4(Wq, wqh, wql, i); return; }
    i -= N4_WQ;
    if (i < N4_WKV) { split4(Wkv, wkh, wkl, i); return; }
    i -= N4_WKV;
    if (i < N4_WO) split4(Wo, woh, wol, i);
}

// ======================= mma.sync bf16x3 GEMM (3-stage pipeline) ==========
#define GK 2048
#define GBK 64
#define NCHUNK (GK / GBK)           // 32
#define TILE_BYTES 16384            // 128 rows * 128B (64 bf16)
#define STAGE_BYTES (4 * TILE_BYTES)

__global__ __launch_bounds__(256, 1) void gemm_bf16x3(
    const __nv_bfloat16* __restrict__ Ah, const __nv_bfloat16* __restrict__ Al,
    const __nv_bfloat16* __restrict__ Wh, const __nv_bfloat16* __restrict__ Wl,
    const float* __restrict__ bias, float* __restrict__ C, int Ndim)
{
    extern __shared__ char smem_raw[];
    char* tiles = (char*)(((uintptr_t)smem_raw + 1023) & ~(uintptr_t)1023);
    const uint32_t tiles_u32 = smem_u32(tiles);

    const int tid  = threadIdx.x;
    const int wid  = tid >> 5;
    const int lane = tid & 31;
    const int bm = blockIdx.y * 128;
    const int bn = blockIdx.x * 128;
    const int wm = (wid & 3) * 32;
    const int wn = (wid >> 2) * 64;

    const __nv_bfloat16* srcs[4] = {Ah, Al, Wh, Wl};

    auto load_chunk = [&](int k0, int s) {
        const uint32_t sb = tiles_u32 + s * STAGE_BYTES;
#pragma unroll
        for (int j = 0; j < 16; j++) {
            int e = tid + j * 256;
            int t = e >> 10;
            int r = (e >> 3) & 127;
            int c = (e & 7) * 8;
            int row = (t < 2 ? bm : bn) + r;
            const void* src = &srcs[t][(size_t)row * GK + k0 + c];
            uint32_t dst = sb + t * TILE_BYTES + SWZ128((uint32_t)(r * 128 + c * 2));
            cp_async16(dst, src);
        }
    };

    float c[2][8][4];
#pragma unroll
    for (int mt = 0; mt < 2; mt++)
#pragma unroll
        for (int nt = 0; nt < 8; nt++)
#pragma unroll
            for (int q = 0; q < 4; q++) c[mt][nt][q] = 0.f;

    const int mi = lane >> 3, rr = lane & 7;

    load_chunk(0, 0);          CP_COMMIT();
    load_chunk(GBK, 1);        CP_COMMIT();

    for (int i = 0; i < NCHUNK; i++) {
        CP_WAIT(1);
        __syncthreads();
        if (i + 2 < NCHUNK) load_chunk((i + 2) * GBK, (i + 2) % 3);
        CP_COMMIT();

        const uint32_t st   = tiles_u32 + (i % 3) * STAGE_BYTES;
        const uint32_t Ah_b = st;
        const uint32_t Al_b = st + TILE_BYTES;
        const uint32_t Wh_b = st + 2 * TILE_BYTES;
        const uint32_t Wl_b = st + 3 * TILE_BYTES;

#pragma unroll
        for (int k16 = 0; k16 < 4; k16++) {
            const int kb = k16 * 16;
            uint32_t ah[2][4], al[2][4], bh[4][4], bl[4][4];
#pragma unroll
            for (int mt = 0; mt < 2; mt++) {
                const int m = wm + mt * 16 + (mi & 1) * 8 + rr;
                const int k = kb + (mi >> 1) * 8;
                const uint32_t off = SWZ128((uint32_t)(m * 128 + k * 2));
                ldsm4(Ah_b + off, ah[mt]);
                ldsm4(Al_b + off, al[mt]);
            }
#pragma unroll
            for (int np = 0; np < 4; np++) {
                const int n = wn + np * 16 + (mi >> 1) * 8 + rr;
                const int k = kb + (mi & 1) * 8;
                const uint32_t off = SWZ128((uint32_t)(n * 128 + k * 2));
                ldsm4(Wh_b + off, bh[np]);
                ldsm4(Wl_b + off, bl[np]);
            }
#pragma unroll
            for (int mt = 0; mt < 2; mt++)
#pragma unroll
                for (int nt = 0; nt < 8; nt++) {
                    const uint32_t* bhp = &bh[nt >> 1][(nt & 1) * 2];
                    const uint32_t* blp = &bl[nt >> 1][(nt & 1) * 2];
                    mma_bf16(c[mt][nt], ah[mt], bhp);
                    mma_bf16(c[mt][nt], ah[mt], blp);
                    mma_bf16(c[mt][nt], al[mt], bhp);
                }
        }
    }

#pragma unroll
    for (int mt = 0; mt < 2; mt++) {
        const int row0 = bm + wm + mt * 16 + (lane >> 2);
#pragma unroll
        for (int nt = 0; nt < 8; nt++) {
            const int col = bn + wn + nt * 8 + (lane & 3) * 2;
            const float b0 = bias[col], b1 = bias[col + 1];
            float2 v0 = make_float2(c[mt][nt][0] + b0, c[mt][nt][1] + b1);
            float2 v1 = make_float2(c[mt][nt][2] + b0, c[mt][nt][3] + b1);
            *(float2*)&C[(size_t)row0 * Ndim + col]       = v0;
            *(float2*)&C[(size_t)(row0 + 8) * Ndim + col] = v1;
        }
    }
}

// ======================= RoPE + split to bf16 hi/lo =======================
__global__ __launch_bounds__(256) void rope_split_cvt(
    const float* __restrict__ cosb, const float* __restrict__ sinb,
    const float* __restrict__ Q, const float* __restrict__ KV,
    __nv_bfloat16* __restrict__ qh, __nv_bfloat16* __restrict__ ql,
    __nv_bfloat16* __restrict__ kh, __nv_bfloat16* __restrict__ kl,
    __nv_bfloat16* __restrict__ vh, __nv_bfloat16* __restrict__ vl)
{
    const int tok = blockIdx.x;
    const int tid = threadIdx.x;
    const float* c = cosb + (size_t)tok * HD;
    const float* s = sinb + (size_t)tok * HD;

    for (int p = tid; p < H * 64; p += 256) {
        const int h = p >> 6, d = p & 63;
        const size_t base = (size_t)tok * D + h * HD;
        const float a = Q[base + d], b2 = Q[base + d + 64];
        const float e0 = (a  * c[d]      - b2 * s[d])      * SCALE;
        const float e1 = (b2 * c[d + 64] + a  * s[d + 64]) * SCALE;
        const float h0 = bf16_round(e0), h1 = bf16_round(e1);
        qh[base + d]      = __float2bfloat16(h0);
        qh[base + d + 64] = __float2bfloat16(h1);
        ql[base + d]      = __float2bfloat16(e0 - h0);
        ql[base + d + 64] = __float2bfloat16(e1 - h1);
    }
    for (int p = tid; p < HKV * 64; p += 256) {
        const int h = p >> 6, d = p & 63;
        const size_t ib = (size_t)tok * KVDIM + h * HD;
        const size_t ob = (size_t)tok * KDIM  + h * HD;
        const float a = KV[ib + d], b2 = KV[ib + d + 64];
        const float e0 = a  * c[d]      - b2 * s[d];
        const float e1 = b2 * c[d + 64] + a  * s[d + 64];
        const float h0 = bf16_round(e0), h1 = bf16_round(e1);
        kh[ob + d]      = __float2bfloat16(h0);
        kh[ob + d + 64] = __float2bfloat16(h1);
        kl[ob + d]      = __float2bfloat16(e0 - h0);
        kl[ob + d + 64] = __float2bfloat16(e1 - h1);
    }
    for (int e = tid; e < KDIM; e += 256) {
        const float v = KV[(size_t)tok * KVDIM + KDIM + e];
        const float h0 = bf16_round(v);
        vh[(size_t)tok * KDIM + e] = __float2bfloat16(h0);
        vl[(size_t)tok * KDIM + e] = __float2bfloat16(v - h0);
    }
}

// ======================= flash attention (tensor cores, bf16x3) ===========
#define FBM 128
#define FBN 64
#define KP  136                       // bf16 per row (pitch)
#define KT_BYTES (FBN * KP * 2)       // 17408
#define FSTG (4 * KT_BYTES)           // Kh,Kl,Vh,Vl per stage

__global__ __launch_bounds__(256, 1) void flash_mma(
    const __nv_bfloat16* __restrict__ Qh, const __nv_bfloat16* __restrict__ Ql,
    const __nv_bfloat16* __restrict__ Kh, const __nv_bfloat16* __restrict__ Kl,
    const __nv_bfloat16* __restrict__ Vh, const __nv_bfloat16* __restrict__ Vl,
    __nv_bfloat16* __restrict__ Ah, __nv_bfloat16* __restrict__ Al)
{
    extern __shared__ char smem_raw[];
    const uint32_t smem = smem_u32(smem_raw);

    const int tid  = threadIdx.x;
    const int w    = tid >> 5;
    const int lane = tid & 31;
    const int m0   = blockIdx.x * FBM;
    const int bh   = blockIdx.y;
    const int b    = bh / H;
    const int h    = bh % H;
    const int kvh  = h / GROUPS;

    const int rowg0 = m0 + w * 16 + (lane >> 2);
    const int rowg1 = rowg0 + 8;

    // ---- Q fragments from global (b,l,h,d layout) ----
    uint32_t qh[8][4], ql[8][4];
    {
        const size_t base0 = ((size_t)(b * L + rowg0) * H + h) * HD;
        const size_t base1 = base0 + (size_t)8 * H * HD;
#pragma unroll
        for (int j = 0; j < 8; j++) {
            const int c0 = j * 16 + (lane & 3) * 2;
            qh[j][0] = *(const uint32_t*)&Qh[base0 + c0];
            qh[j][1] = *(const uint32_t*)&Qh[base1 + c0];
            qh[j][2] = *(const uint32_t*)&Qh[base0 + c0 + 8];
            qh[j][3] = *(const uint32_t*)&Qh[base1 + c0 + 8];
            ql[j][0] = *(const uint32_t*)&Ql[base0 + c0];
            ql[j][1] = *(const uint32_t*)&Ql[base1 + c0];
            ql[j][2] = *(const uint32_t*)&Ql[base0 + c0 + 8];
            ql[j][3] = *(const uint32_t*)&Ql[base1 + c0 + 8];
        }
    }

    const __nv_bfloat16* kvsrc[4] = {Kh, Kl, Vh, Vl};
    auto load_kv = [&](int t, int s) {
        const int n0 = t * FBN;
        const uint32_t sb = smem + s * FSTG;
#pragma unroll
        for (int jj = 0; jj < 16; jj++) {
            int e = tid + jj * 256;
            int buf = e >> 10;
            int r   = (e >> 4) & 63;
            int ch  = e & 15;
            const void* src =
                &kvsrc[buf][((size_t)(b * L + n0 + r) * HKV + kvh) * HD + ch * 8];
            uint32_t dst = sb + buf * KT_BYTES + (uint32_t)(r * KP + ch * 8) * 2;
            cp_async16(dst, src);
        }
    };

    float o[16][4];
#pragma unroll
    for (int nt = 0; nt < 16; nt++)
#pragma unroll
        for (int q = 0; q < 4; q++) o[nt][q] = 0.f;
    float mrow0 = -1e30f, mrow1 = -1e30f, lrow0 = 0.f, lrow1 = 0.f;

    const int ntiles = m0 / FBN + 2;
    load_kv(0, 0);
    CP_COMMIT();

    const int rlane = lane & 7;
    const int khalf = (lane >> 3) & 1;
    const int npair = lane >> 4;          // 0/1: which tile of the ldsm4 pair

    for (int t = 0; t < ntiles; t++) {
        CP_WAIT(0);
        __syncthreads();
        if (t + 1 < ntiles) load_kv(t + 1, (t + 1) & 1);
        CP_COMMIT();

        const int n0 = t * FBN;
        if (n0 > m0 + w * 16 + 15) continue;

        const uint32_t st  = smem + (t & 1) * FSTG;
        const uint32_t Khs = st;
        const uint32_t Kls = st + KT_BYTES;
        const uint32_t Vhs = st + 2 * KT_BYTES;
        const uint32_t Vls = st + 3 * KT_BYTES;

        // ---- scores (ldsm4 pairs two n-tiles) ----
        float s8[8][4];
#pragma unroll
        for (int nt = 0; nt < 8; nt++)
#pragma unroll
            for (int q = 0; q < 4; q++) s8[nt][q] = 0.f;

#pragma unroll
        for (int j = 0; j < 8; j++) {
#pragma unroll
            for (int nt = 0; nt < 8; nt += 2) {
                uint32_t kb4[4], kl4[4];
                const uint32_t a = (uint32_t)(((nt + npair) * 8 + rlane) * KP
                                              + j * 16 + khalf * 8) * 2;
                ldsm4(Khs + a, kb4);
                ldsm4(Kls + a, kl4);
                mma_bf16(s8[nt],     qh[j], kb4);
                mma_bf16(s8[nt],     qh[j], kl4);
                mma_bf16(s8[nt],     ql[j], kb4);
                mma_bf16(s8[nt + 1], qh[j], kb4 + 2);
                mma_bf16(s8[nt + 1], qh[j], kl4 + 2);
                mma_bf16(s8[nt + 1], ql[j], kb4 + 2);
            }
        }

        // ---- causal mask (near diagonal only) ----
        if (t >= ntiles - 2) {
            const int colc = n0 + (lane & 3) * 2;
#pragma unroll
            for (int nt = 0; nt < 8; nt++) {
                const int cg = colc + nt * 8;
                if (cg     > rowg0) s8[nt][0] = -1e30f;
                if (cg + 1 > rowg0) s8[nt][1] = -1e30f;
                if (cg     > rowg1) s8[nt][2] = -1e30f;
                if (cg + 1 > rowg1) s8[nt][3] = -1e30f;
            }
        }

        // ---- online softmax ----
        float mx0 = -1e30f, mx1 = -1e30f;
#pragma unroll
        for (int nt = 0; nt < 8; nt++) {
            mx0 = fmaxf(mx0, fmaxf(s8[nt][0], s8[nt][1]));
            mx1 = fmaxf(mx1, fmaxf(s8[nt][2], s8[nt][3]));
        }
        mx0 = fmaxf(mx0, __shfl_xor_sync(0xffffffffu, mx0, 1));
        mx0 = fmaxf(mx0, __shfl_xor_sync(0xffffffffu, mx0, 2));
        mx1 = fmaxf(mx1, __shfl_xor_sync(0xffffffffu, mx1, 1));
        mx1 = fmaxf(mx1, __shfl_xor_sync(0xffffffffu, mx1, 2));

        const float mn0 = fmaxf(mrow0, mx0);
        const float mn1 = fmaxf(mrow1, mx1);
        const float alpha0 = __expf(mrow0 - mn0);
        const float alpha1 = __expf(mrow1 - mn1);

        float sum0 = 0.f, sum1 = 0.f;
#pragma unroll
        for (int nt = 0; nt < 8; nt++) {
            s8[nt][0] = __expf(s8[nt][0] - mn0);
            s8[nt][1] = __expf(s8[nt][1] - mn0);
            s8[nt][2] = __expf(s8[nt][2] - mn1);
            s8[nt][3] = __expf(s8[nt][3] - mn1);
            sum0 += s8[nt][0] + s8[nt][1];
            sum1 += s8[nt][2] + s8[nt][3];
        }
        sum0 += __shfl_xor_sync(0xffffffffu, sum0, 1);
        sum0 += __shfl_xor_sync(0xffffffffu, sum0, 2);
        sum1 += __shfl_xor_sync(0xffffffffu, sum1, 1);
        sum1 += __shfl_xor_sync(0xffffffffu, sum1, 2);

        lrow0 = lrow0 * alpha0 + sum0;
        lrow1 = lrow1 * alpha1 + sum1;
        mrow0 = mn0; mrow1 = mn1;

#pragma unroll
        for (int nt = 0; nt < 16; nt++) {
            o[nt][0] *= alpha0; o[nt][1] *= alpha0;
            o[nt][2] *= alpha1; o[nt][3] *= alpha1;
        }

        // ---- P·V (ldsm4t pairs two n-tiles) ----
#pragma unroll
        for (int kt = 0; kt < 4; kt++) {
            uint32_t ph4[4], pl4[4];
            {
                const float* p0 = s8[2 * kt];
                const float* p1 = s8[2 * kt + 1];
                float h;
                h = bf16_round(p0[0]); float l00 = p0[0] - h;
                h = bf16_round(p0[1]); float l01 = p0[1] - h;
                h = bf16_round(p0[2]); float l02 = p0[2] - h;
                h = bf16_round(p0[3]); float l03 = p0[3] - h;
                ph4[0] = pack_bf16x2(p0[0], p0[1]);
                ph4[1] = pack_bf16x2(p0[2], p0[3]);
                pl4[0] = pack_bf16x2(l00, l01);
                pl4[1] = pack_bf16x2(l02, l03);
                h = bf16_round(p1[0]); float l10 = p1[0] - h;
                h = bf16_round(p1[1]); float l11 = p1[1] - h;
                h = bf16_round(p1[2]); float l12 = p1[2] - h;
                h = bf16_round(p1[3]); float l13 = p1[3] - h;
                ph4[2] = pack_bf16x2(p1[0], p1[1]);
                ph4[3] = pack_bf16x2(p1[2], p1[3]);
                pl4[2] = pack_bf16x2(l10, l11);
                pl4[3] = pack_bf16x2(l12, l13);
            }
#pragma unroll
            for (int nt = 0; nt < 16; nt += 2) {
                uint32_t vh4[4], vl4[4];
                const uint32_t a = (uint32_t)((kt * 16 + khalf * 8 + rlane) * KP
                                              + (nt + npair) * 8) * 2;
                ldsm4t(Vhs + a, vh4);
                ldsm4t(Vls + a, vl4);
                mma_bf16(o[nt],     ph4, vh4);
                mma_bf16(o[nt],     ph4, vl4);
                mma_bf16(o[nt],     pl4, vh4);
                mma_bf16(o[nt + 1], ph4, vh4 + 2);
                mma_bf16(o[nt + 1], ph4, vl4 + 2);
                mma_bf16(o[nt + 1], pl4, vh4 + 2);
            }
        }
    }

    // ---- epilogue: normalize, split, store (b,l,h,d) ----
    const float inv0 = 1.f / lrow0;
    const float inv1 = 1.f / lrow1;
    const size_t base0 = ((size_t)(b * L + rowg0) * H + h) * HD;
    const size_t base1 = base0 + (size_t)8 * H * HD;
#pragma unroll
    for (int nt = 0; nt < 16; nt++) {
        const int col = nt * 8 + (lane & 3) * 2;
        const float f0 = o[nt][0] * inv0, f1 = o[nt][1] * inv0;
        const float f2 = o[nt][2] * inv1, f3 = o[nt][3] * inv1;
        const float h0 = bf16_round(f0), h1 = bf16_round(f1);
        const float h2 = bf16_round(f2), h3 = bf16_round(f3);
        *(uint32_t*)&Ah[base0 + col] = pack_bf16x2(f0, f1);
        *(uint32_t*)&Ah[base1 + col] = pack_bf16x2(f2, f3);
        *(uint32_t*)&Al[base0 + col] = pack_bf16x2(f0 - h0, f1 - h1);
        *(uint32_t*)&Al[base1 + col] = pack_bf16x2(f2 - h2, f3 - h3);
    }
}

// ===========================================================================
extern "C" void kernel_launch(void* const* d_in, const int* in_sizes, int n_in,
                              void* d_out, int out_size)
{
    (void)in_sizes; (void)n_in; (void)out_size;
    const float* x    = (const float*)d_in[0];
    const float* cosb = (const float*)d_in[1];
    const float* sinb = (const float*)d_in[2];
    const float* Wq   = (const float*)d_in[3];
    const float* bq   = (const float*)d_in[4];
    const float* Wkv  = (const float*)d_in[5];
    const float* bkv  = (const float*)d_in[6];
    const float* Wo   = (const float*)d_in[7];
    const float* bo   = (const float*)d_in[8];
    float* out = (float*)d_out;

    float *Qb, *KVb;
    __nv_bfloat16 *xh, *xl, *wqh, *wql, *wkh, *wkl, *woh, *wol;
    __nv_bfloat16 *qh, *ql, *kh, *kl, *vh, *vl, *ah, *al;
    cudaGetSymbolAddress((void**)&Qb,  g_Q);
    cudaGetSymbolAddress((void**)&KVb, g_KV);
    cudaGetSymbolAddress((void**)&xh,  g_xh);
    cudaGetSymbolAddress((void**)&xl,  g_xl);
    cudaGetSymbolAddress((void**)&wqh, g_wqh);
    cudaGetSymbolAddress((void**)&wql, g_wql);
    cudaGetSymbolAddress((void**)&wkh, g_wkh);
    cudaGetSymbolAddress((void**)&wkl, g_wkl);
    cudaGetSymbolAddress((void**)&woh, g_woh);
    cudaGetSymbolAddress((void**)&wol, g_wol);
    cudaGetSymbolAddress((void**)&qh,  g_qh);
    cudaGetSymbolAddress((void**)&ql,  g_ql);
    cudaGetSymbolAddress((void**)&kh,  g_kh);
    cudaGetSymbolAddress((void**)&kl,  g_kl);
    cudaGetSymbolAddress((void**)&vh,  g_vh);
    cudaGetSymbolAddress((void**)&vl,  g_vl);
    cudaGetSymbolAddress((void**)&ah,  g_ah);
    cudaGetSymbolAddress((void**)&al,  g_al);

    const int gemm_smem = 1024 + 3 * STAGE_BYTES;
    cudaFuncSetAttribute(gemm_bf16x3, cudaFuncAttributeMaxDynamicSharedMemorySize,
                         gemm_smem);
    const int fa_smem = 2 * FSTG;
    cudaFuncSetAttribute(flash_mma, cudaFuncAttributeMaxDynamicSharedMemorySize,
                         fa_smem);

    // one fused conversion for x + all weights
    cvt_all<<<(N4_TOT + 255) / 256, 256>>>(x, Wq, Wkv, Wo,
                                           xh, xl, wqh, wql, wkh, wkl, woh, wol);

    // Q projection
    gemm_bf16x3<<<dim3(D / 128, M_TOK / 128), 256, gemm_smem>>>(
        xh, xl, wqh, wql, bq, Qb, D);

    // KV projection
    gemm_bf16x3<<<dim3(KVDIM / 128, M_TOK / 128), 256, gemm_smem>>>(
        xh, xl, wkh, wkl, bkv, KVb, KVDIM);

    // RoPE + split to bf16 hi/lo (scale folded into Q)
    rope_split_cvt<<<M_TOK, 256>>>(cosb, sinb, Qb, KVb, qh, ql, kh, kl, vh, vl);

    // tensor-core flash attention -> Ah/Al splits
    flash_mma<<<dim3(L / FBM, B * H), 256, fa_smem>>>(
        qh, ql, kh, kl, vh, vl, ah, al);

    // O projection
    gemm_bf16x3<<<dim3(D / 128, M_TOK / 128), 256, gemm_smem>>>(
        ah, al, woh, wol, bo, out, D);
}